// round 15
// baseline (speedup 1.0000x reference)
#include <cuda_runtime.h>
#include <cuda_bf16.h>
#include <cstdint>

// ---------------------------------------------------------------------------
// SchNet interaction block, sm_103 — v15: v14 + pre-split A in K2 (occ 1).
//   prep:  ALL weights -> pre-swizzled bf16 hi/lo chunk images (prep_all)
//   K1:    XF = x @ W_in2f                        (k1_hmma, M=32/CTA)
//   K2:    fused filter MLP + gather + aggregate  (k2_hmma, pre-split A)
//   K3:    ssp((Y@Wf2o+b)@Wd + G@Wang + b)        (tail_hmma, M=32/CTA)
// GEMMs: D += Ahi*Bhi + Ahi*Blo + Alo*Bhi (bf16 splits, fp32 acc).
// v15: K2's A operands (F, then H) are split to packed bf16x2 hi/lo ONCE and
// kept in smem (stride 132 words, conflict-free); the MMA loop does plain
// LDS.32 A-fragment loads with zero conversion work.
// ---------------------------------------------------------------------------

#define BDIM 256
#define NATOMS 4096
#define CUTOFF 5.0f

// K2 smem layout (bytes)
#define KPS        132                 // A row stride in uint32 kpairs
#define SAL_OFF    33792               // 64*132*4
#define SLOT_OFF   67584
#define BUF_BYTES  16384
#define SMEM_M_OFF 100352
#define SMEM_R_OFF 100608
#define SMEM_RED_OFF 100864
#define SMEM_K2_TOTAL 102912
#define SXFS       260                 // XF gather row stride (floats)

// K1 smem
#define SXS        260
#define K1_SLOT_OFF 33280
#define SMEM_K1_TOTAL 66048
// tail smem
#define T_SLOT_OFF 66560
#define SMEM_T_TOTAL 99328

__device__ float g_XF[NATOMS * 256];
__device__ float g_Y [NATOMS * 256];
__device__ __align__(16) uint4 g_w1s[8 * 1024];
__device__ __align__(16) uint4 g_w2s[16 * 1024];
__device__ __align__(16) uint4 g_wis[16 * 1024];
__device__ __align__(16) uint4 g_wfs[16 * 1024];
__device__ __align__(16) uint4 g_wdg[24 * 1024];

// ================= helpers =================

__device__ __forceinline__ uint32_t smem_u32(const void* p) {
    uint32_t a;
    asm("{ .reg .u64 t; cvta.to.shared.u64 t, %1; cvt.u32.u64 %0, t; }" : "=r"(a) : "l"(p));
    return a;
}
__device__ __forceinline__ float sspf(float v) {
    float e = __expf(v);
    float r = __logf(fmaf(0.5f, e, 0.5f));
    return (v > 60.0f) ? (v - 0.69314718055994531f) : r;
}
__device__ __forceinline__ uint32_t pack_bf2(float v0, float v1) {
    uint32_t r;
    asm("cvt.rn.satfinite.bf16x2.f32 %0, %1, %2;" : "=r"(r) : "f"(v1), "f"(v0));
    return r;
}
__device__ __forceinline__ float bf2_lo(uint32_t p) { return __uint_as_float(p << 16); }
__device__ __forceinline__ float bf2_hi(uint32_t p) { return __uint_as_float(p & 0xffff0000u); }

__device__ __forceinline__ void mma_bf16(float* d, uint32_t a0, uint32_t a1, uint32_t a2, uint32_t a3,
                                         uint32_t b0, uint32_t b1) {
    asm volatile("mma.sync.aligned.m16n8k16.row.col.f32.bf16.bf16.f32 "
                 "{%0,%1,%2,%3}, {%4,%5,%6,%7}, {%8,%9}, {%0,%1,%2,%3};"
                 : "+f"(d[0]), "+f"(d[1]), "+f"(d[2]), "+f"(d[3])
                 : "r"(a0), "r"(a1), "r"(a2), "r"(a3), "r"(b0), "r"(b1));
}

__device__ __forceinline__ void cp16(uint32_t dst, const void* src) {
    asm volatile("cp.async.cg.shared.global [%0], [%1], 16;" :: "r"(dst), "l"(src) : "memory");
}
#define CP_COMMIT() asm volatile("cp.async.commit_group;" ::: "memory")
#define CP_WAIT0()  asm volatile("cp.async.wait_group 0;" ::: "memory")

__device__ __forceinline__ void stage_at(uint32_t dstaddr, const uint4* ws, int s, int tid) {
    uint32_t d = dstaddr + (uint32_t)tid * 64;
    const char* g = (const char*)(ws + s * 1024) + tid * 64;
    cp16(d,      g);
    cp16(d + 16, g + 16);
    cp16(d + 32, g + 32);
    cp16(d + 48, g + 48);
}

// K2 kstep: A pre-split in sAh/sAl (packed bf16x2 kpairs), zero conversions.
__device__ __forceinline__ void gemm_kstep_ps(float (&acc)[2][8][4],
                                              const uint32_t* sAh, const uint32_t* sAl,
                                              int s, const char* slot,
                                              int mt, int nb, int q, int c, int slSel) {
    const int kp = 8 * s + c;
    uint32_t ah[2][4], al[2][4];
    #pragma unroll
    for (int t = 0; t < 2; ++t) {
        const int r0 = (mt * 32 + t * 16 + q) * KPS;
        const int r8 = r0 + 8 * KPS;
        ah[t][0] = sAh[r0 + kp];     ah[t][1] = sAh[r8 + kp];
        ah[t][2] = sAh[r0 + kp + 4]; ah[t][3] = sAh[r8 + kp + 4];
        al[t][0] = sAl[r0 + kp];     al[t][1] = sAl[r8 + kp];
        al[t][2] = sAl[r0 + kp + 4]; al[t][3] = sAl[r8 + kp + 4];
    }
    #pragma unroll
    for (int nt = 0; nt < 8; ++nt) {
        const int f = nb * 64 + nt * 8 + q;
        uint4 B = *(const uint4*)(slot + f * 64 + slSel * 16);
        mma_bf16(acc[0][nt], ah[0][0], ah[0][1], ah[0][2], ah[0][3], B.x, B.y);
        mma_bf16(acc[0][nt], ah[0][0], ah[0][1], ah[0][2], ah[0][3], B.z, B.w);
        mma_bf16(acc[0][nt], al[0][0], al[0][1], al[0][2], al[0][3], B.x, B.y);
        mma_bf16(acc[1][nt], ah[1][0], ah[1][1], ah[1][2], ah[1][3], B.x, B.y);
        mma_bf16(acc[1][nt], ah[1][0], ah[1][1], ah[1][2], ah[1][3], B.z, B.w);
        mma_bf16(acc[1][nt], al[1][0], al[1][1], al[1][2], al[1][3], B.x, B.y);
    }
}

// M=32 kstep with live split (K1/tail; conversion cost negligible there)
__device__ __forceinline__ void gemm_kstep32(float (&acc)[2][4][4], const float* sX, int rowbase,
                                             int k0, const char* slot, int nb, int q, int c,
                                             int slSel) {
    uint32_t ah[2][4], al[2][4];
    #pragma unroll
    for (int t = 0; t < 2; ++t) {
        const float* bp = sX + (rowbase + t * 16 + q) * SXS + k0 + 2 * c;
        float2 v0 = *(const float2*)(bp);
        float2 v1 = *(const float2*)(bp + 8 * SXS);
        float2 v2 = *(const float2*)(bp + 8);
        float2 v3 = *(const float2*)(bp + 8 * SXS + 8);
        ah[t][0] = pack_bf2(v0.x, v0.y); al[t][0] = pack_bf2(v0.x - bf2_lo(ah[t][0]), v0.y - bf2_hi(ah[t][0]));
        ah[t][1] = pack_bf2(v1.x, v1.y); al[t][1] = pack_bf2(v1.x - bf2_lo(ah[t][1]), v1.y - bf2_hi(ah[t][1]));
        ah[t][2] = pack_bf2(v2.x, v2.y); al[t][2] = pack_bf2(v2.x - bf2_lo(ah[t][2]), v2.y - bf2_hi(ah[t][2]));
        ah[t][3] = pack_bf2(v3.x, v3.y); al[t][3] = pack_bf2(v3.x - bf2_lo(ah[t][3]), v3.y - bf2_hi(ah[t][3]));
    }
    #pragma unroll
    for (int nt = 0; nt < 4; ++nt) {
        const int f = nb * 32 + nt * 8 + q;
        uint4 B = *(const uint4*)(slot + f * 64 + slSel * 16);
        mma_bf16(acc[0][nt], ah[0][0], ah[0][1], ah[0][2], ah[0][3], B.x, B.y);
        mma_bf16(acc[0][nt], ah[0][0], ah[0][1], ah[0][2], ah[0][3], B.z, B.w);
        mma_bf16(acc[0][nt], al[0][0], al[0][1], al[0][2], al[0][3], B.x, B.y);
        mma_bf16(acc[1][nt], ah[1][0], ah[1][1], ah[1][2], ah[1][3], B.x, B.y);
        mma_bf16(acc[1][nt], ah[1][0], ah[1][1], ah[1][2], ah[1][3], B.z, B.w);
        mma_bf16(acc[1][nt], al[1][0], al[1][1], al[1][2], al[1][3], B.x, B.y);
    }
}

// ================= prep: ALL weights in one launch =================

__global__ void prep_all(const float* __restrict__ W1, const float* __restrict__ W2,
                         const float* __restrict__ Wi, const float* __restrict__ Wf,
                         const float* __restrict__ Wd, const float* __restrict__ Wa,
                         uint4* __restrict__ p1s, uint4* __restrict__ p2s,
                         uint4* __restrict__ pis, uint4* __restrict__ pfs,
                         uint4* __restrict__ pdg)
{
    int i = blockIdx.x * 256 + threadIdx.x;
    const float* W; uint4* dst; int idx;
    if      (i < 8192)  { W = W1; dst = p1s;             idx = i; }
    else if (i < 24576) { W = W2; dst = p2s;             idx = i - 8192; }
    else if (i < 40960) { W = Wi; dst = pis;             idx = i - 24576; }
    else if (i < 57344) { W = Wf; dst = pfs;             idx = i - 40960; }
    else if (i < 73728) { W = Wd; dst = pdg;             idx = i - 57344; }
    else if (i < 81920) { W = Wa; dst = pdg + 16 * 1024; idx = i - 73728; }
    else return;
    const int s = idx >> 10;
    const int r = idx & 1023;
    const int f = r >> 2;
    const int slotIdx = r & 3;
    const int c = (slotIdx - (f >> 1)) & 3;
    const int k0 = s * 16 + 2 * c;
    float v0 = W[(size_t)(k0)     * 256 + f];
    float v1 = W[(size_t)(k0 + 1) * 256 + f];
    float v2 = W[(size_t)(k0 + 8) * 256 + f];
    float v3 = W[(size_t)(k0 + 9) * 256 + f];
    uint32_t h0 = pack_bf2(v0, v1);
    uint32_t h1 = pack_bf2(v2, v3);
    uint32_t l0 = pack_bf2(v0 - bf2_lo(h0), v1 - bf2_hi(h0));
    uint32_t l1 = pack_bf2(v2 - bf2_lo(h1), v3 - bf2_hi(h1));
    dst[s * 1024 + f * 4 + slotIdx] = make_uint4(h0, h1, l0, l1);
}

// ================= K2: HMMA fused filter, pre-split A (occ 1) ===============

__global__ __launch_bounds__(BDIM)
void k2_hmma(const float* __restrict__ f_ij, const float* __restrict__ r_ij,
             const float* __restrict__ nmask, const int* __restrict__ neigh,
             const uint4* __restrict__ w1s, const uint4* __restrict__ w2s,
             const float* __restrict__ b1, const float* __restrict__ b2,
             const float* __restrict__ XF, float* __restrict__ Y)
{
    extern __shared__ char smc[];
    uint32_t* sAh = (uint32_t*)smc;
    uint32_t* sAl = (uint32_t*)(smc + SAL_OFF);
    float* sXF  = (float*)smc;                // post-GEMM2 reuse (stride SXFS)
    float* sM   = (float*)(smc + SMEM_M_OFF);
    int*   sRow = (int*)  (smc + SMEM_R_OFF);
    float* sRed = (float*)(smc + SMEM_RED_OFF);
    const uint32_t sbase = smem_u32(smc);
    const int tid = threadIdx.x, wid = tid >> 5, lane = tid & 31;
    const int q = lane >> 2, c = lane & 3;
    const int slSel = (c + (q >> 1)) & 3;
    const int mt = wid & 1, nb = wid >> 1;
    const int bid = blockIdx.x;

    // kick off W1 chunk 0
    stage_at(sbase + SLOT_OFF, w1s, 0, tid);
    CP_COMMIT();

    // F [64][128] fp32 -> packed bf16 hi/lo kpairs (split once)
    {
        const float4* f4 = (const float4*)(f_ij + (size_t)bid * 8192);
        #pragma unroll
        for (int u = 0; u < 8; ++u) {
            int i4 = tid + u * 256;
            int row = i4 >> 5, c4 = i4 & 31;
            float4 v = f4[i4];
            uint32_t h0 = pack_bf2(v.x, v.y);
            uint32_t h1 = pack_bf2(v.z, v.w);
            uint32_t l0 = pack_bf2(v.x - bf2_lo(h0), v.y - bf2_hi(h0));
            uint32_t l1 = pack_bf2(v.z - bf2_lo(h1), v.w - bf2_hi(h1));
            *(uint2*)&sAh[row * KPS + 2 * c4] = make_uint2(h0, h1);
            *(uint2*)&sAl[row * KPS + 2 * c4] = make_uint2(l0, l1);
        }
    }
    if (tid < 64) {
        float r = r_ij[bid * 64 + tid];
        float m = nmask[bid * 64 + tid];
        sM[tid]   = (r <= CUTOFF) ? m : 0.0f;
        sRow[tid] = (bid >> 9) * 512 + neigh[bid * 64 + tid];
    }

    float acc[2][8][4];
    #pragma unroll
    for (int a = 0; a < 2; ++a)
        #pragma unroll
        for (int n = 0; n < 8; ++n)
            #pragma unroll
            for (int i = 0; i < 4; ++i) acc[a][n][i] = 0.0f;

    // ---- GEMM1: P = F @ W1 (8 ksteps) ----
    #pragma unroll 1
    for (int s = 0; s < 8; ++s) {
        CP_WAIT0();
        __syncthreads();
        if (s < 7) { stage_at(sbase + SLOT_OFF + ((s + 1) & 1) * BUF_BYTES, w1s, s + 1, tid); CP_COMMIT(); }
        gemm_kstep_ps(acc, sAh, sAl, s, smc + SLOT_OFF + (s & 1) * BUF_BYTES, mt, nb, q, c, slSel);
    }
    __syncthreads();

    stage_at(sbase + SLOT_OFF, w2s, 0, tid);
    CP_COMMIT();

    // ---- H = ssp(P + b1) -> packed hi/lo (split once in epilogue) ----
    #pragma unroll
    for (int nt = 0; nt < 8; ++nt) {
        const int col = nb * 64 + nt * 8 + 2 * c;
        const int kp  = col >> 1;
        float2 bv = *(const float2*)(b1 + col);
        #pragma unroll
        for (int t = 0; t < 2; ++t) {
            const int r0 = mt * 32 + t * 16 + q;
            float v0 = sspf(acc[t][nt][0] + bv.x);
            float v1 = sspf(acc[t][nt][1] + bv.y);
            float v2 = sspf(acc[t][nt][2] + bv.x);
            float v3 = sspf(acc[t][nt][3] + bv.y);
            uint32_t h0 = pack_bf2(v0, v1);
            uint32_t h1 = pack_bf2(v2, v3);
            sAh[r0 * KPS + kp]       = h0;
            sAh[(r0 + 8) * KPS + kp] = h1;
            sAl[r0 * KPS + kp]       = pack_bf2(v0 - bf2_lo(h0), v1 - bf2_hi(h0));
            sAl[(r0 + 8) * KPS + kp] = pack_bf2(v2 - bf2_lo(h1), v3 - bf2_hi(h1));
        }
    }
    #pragma unroll
    for (int a = 0; a < 2; ++a)
        #pragma unroll
        for (int n = 0; n < 8; ++n)
            #pragma unroll
            for (int i = 0; i < 4; ++i) acc[a][n][i] = 0.0f;

    // ---- GEMM2: Wf = H @ W2 (16 ksteps) ----
    #pragma unroll 1
    for (int s = 0; s < 16; ++s) {
        CP_WAIT0();
        __syncthreads();
        if (s < 15) { stage_at(sbase + SLOT_OFF + ((s + 1) & 1) * BUF_BYTES, w2s, s + 1, tid); CP_COMMIT(); }
        gemm_kstep_ps(acc, sAh, sAl, s, smc + SLOT_OFF + (s & 1) * BUF_BYTES, mt, nb, q, c, slSel);
    }
    __syncthreads();

    // ---- gather XF rows via cp.async (A region dead) ----
    #pragma unroll
    for (int rr = 0; rr < 8; ++rr) {
        const int row = wid * 8 + rr;
        const char* src = (const char*)(XF + (size_t)sRow[row] * 256);
        cp16(sbase + (uint32_t)(row * 1040) + lane * 16,       src + lane * 16);
        cp16(sbase + (uint32_t)(row * 1040) + 512 + lane * 16, src + 512 + lane * 16);
    }
    CP_COMMIT();
    CP_WAIT0();
    __syncthreads();

    // ---- epilogue: y[col] = sum_rows m*(Wf + b2)*xf ----
    #pragma unroll
    for (int nt = 0; nt < 8; ++nt) {
        const int col = nb * 64 + nt * 8 + 2 * c;
        float2 bv = *(const float2*)(b2 + col);
        float pe = 0.0f, po = 0.0f;
        #pragma unroll
        for (int t = 0; t < 2; ++t) {
            #pragma unroll
            for (int p = 0; p < 2; ++p) {
                const int row = mt * 32 + t * 16 + q + 8 * p;
                const float m = sM[row];
                float2 x = *(const float2*)(sXF + row * SXFS + col);
                pe = fmaf(m * (acc[t][nt][2 * p]     + bv.x), x.x, pe);
                po = fmaf(m * (acc[t][nt][2 * p + 1] + bv.y), x.y, po);
            }
        }
        pe += __shfl_xor_sync(0xffffffffu, pe, 4);
        pe += __shfl_xor_sync(0xffffffffu, pe, 8);
        pe += __shfl_xor_sync(0xffffffffu, pe, 16);
        po += __shfl_xor_sync(0xffffffffu, po, 4);
        po += __shfl_xor_sync(0xffffffffu, po, 8);
        po += __shfl_xor_sync(0xffffffffu, po, 16);
        if (q == nt) {
            sRed[mt * 256 + col]     = pe;
            sRed[mt * 256 + col + 1] = po;
        }
    }
    __syncthreads();
    Y[(size_t)bid * 256 + tid] = sRed[tid] + sRed[256 + tid];
}

// ================= K1: XF = x @ W_in2f (HMMA, M=32/CTA) =================

__global__ __launch_bounds__(BDIM)
void k1_hmma(const float* __restrict__ x, const uint4* __restrict__ wis,
             float* __restrict__ XF)
{
    extern __shared__ char smc[];
    float* sX = (float*)smc;
    const uint32_t sbase = smem_u32(smc);
    const int tid = threadIdx.x, wid = tid >> 5, lane = tid & 31;
    const int q = lane >> 2, c = lane & 3;
    const int slSel = (c + (q >> 1)) & 3;
    const int nb = wid;
    const int bid = blockIdx.x;

    stage_at(sbase + K1_SLOT_OFF, wis, 0, tid);
    {
        const char* xg = (const char*)(x + (size_t)bid * 8192);
        #pragma unroll
        for (int u = 0; u < 8; ++u) {
            int unit = tid + u * 256;
            int row = unit >> 6, c16 = unit & 63;
            cp16(sbase + (uint32_t)(row * 1040 + c16 * 16), xg + unit * 16);
        }
    }
    CP_COMMIT();

    float acc[2][4][4];
    #pragma unroll
    for (int a = 0; a < 2; ++a)
        #pragma unroll
        for (int n = 0; n < 4; ++n)
            #pragma unroll
            for (int i = 0; i < 4; ++i) acc[a][n][i] = 0.0f;

    #pragma unroll 1
    for (int s = 0; s < 16; ++s) {
        CP_WAIT0();
        __syncthreads();
        if (s < 15) { stage_at(sbase + K1_SLOT_OFF + ((s + 1) & 1) * BUF_BYTES, wis, s + 1, tid); CP_COMMIT(); }
        gemm_kstep32(acc, sX, 0, s * 16, smc + K1_SLOT_OFF + (s & 1) * BUF_BYTES, nb, q, c, slSel);
    }
    __syncthreads();

    #pragma unroll
    for (int nt = 0; nt < 4; ++nt) {
        const int col = nb * 32 + nt * 8 + 2 * c;
        #pragma unroll
        for (int t = 0; t < 2; ++t) {
            const int r0 = t * 16 + q;
            *(float2*)(sX + r0 * SXS + col)       = make_float2(acc[t][nt][0], acc[t][nt][1]);
            *(float2*)(sX + (r0 + 8) * SXS + col) = make_float2(acc[t][nt][2], acc[t][nt][3]);
        }
    }
    __syncthreads();
    {
        float4* dst = (float4*)(XF + (size_t)bid * 8192);
        #pragma unroll
        for (int u = 0; u < 8; ++u) {
            int i4 = tid + u * 256;
            int row = i4 >> 6, c4 = i4 & 63;
            dst[i4] = *(const float4*)(sX + row * SXS + c4 * 4);
        }
    }
}

// ================= K3: tail (HMMA, M=32/CTA) =================

__global__ __launch_bounds__(BDIM)
void tail_hmma(const float* __restrict__ Yin, const float* __restrict__ Gin,
               const uint4* __restrict__ wfs, const float* __restrict__ bf,
               const uint4* __restrict__ wdg, const float* __restrict__ bd,
               float* __restrict__ out)
{
    extern __shared__ char smc[];
    float* sX = (float*)smc;
    const uint32_t sbase = smem_u32(smc);
    const int tid = threadIdx.x, wid = tid >> 5, lane = tid & 31;
    const int q = lane >> 2, c = lane & 3;
    const int slSel = (c + (q >> 1)) & 3;
    const int nb = wid;
    const int bid = blockIdx.x;

    stage_at(sbase + T_SLOT_OFF, wfs, 0, tid);
    {
        const char* yg = (const char*)(Yin + (size_t)bid * 8192);
        #pragma unroll
        for (int u = 0; u < 8; ++u) {
            int unit = tid + u * 256;
            int row = unit >> 6, c16 = unit & 63;
            cp16(sbase + (uint32_t)(row * 1040 + c16 * 16), yg + unit * 16);
        }
        const char* gg = (const char*)(Gin + (size_t)bid * 4096);
        #pragma unroll
        for (int u = 0; u < 4; ++u) {
            int unit = tid + u * 256;
            int row = unit >> 5, c16 = unit & 31;
            cp16(sbase + (uint32_t)((32 + row) * 1040 + c16 * 16), gg + unit * 16);
        }
    }
    CP_COMMIT();

    float acc[2][4][4];
    #pragma unroll
    for (int a = 0; a < 2; ++a)
        #pragma unroll
        for (int n = 0; n < 4; ++n)
            #pragma unroll
            for (int i = 0; i < 4; ++i) acc[a][n][i] = 0.0f;

    #pragma unroll 1
    for (int s = 0; s < 16; ++s) {
        CP_WAIT0();
        __syncthreads();
        if (s < 15) { stage_at(sbase + T_SLOT_OFF + ((s + 1) & 1) * BUF_BYTES, wfs, s + 1, tid); CP_COMMIT(); }
        gemm_kstep32(acc, sX, 0, s * 16, smc + T_SLOT_OFF + (s & 1) * BUF_BYTES, nb, q, c, slSel);
    }
    __syncthreads();

    stage_at(sbase + T_SLOT_OFF, wdg, 0, tid);
    CP_COMMIT();

    #pragma unroll
    for (int nt = 0; nt < 4; ++nt) {
        const int col = nb * 32 + nt * 8 + 2 * c;
        float2 bv = *(const float2*)(bf + col);
        #pragma unroll
        for (int t = 0; t < 2; ++t) {
            const int r0 = t * 16 + q;
            *(float2*)(sX + r0 * SXS + col) =
                make_float2(acc[t][nt][0] + bv.x, acc[t][nt][1] + bv.y);
            *(float2*)(sX + (r0 + 8) * SXS + col) =
                make_float2(acc[t][nt][2] + bv.x, acc[t][nt][3] + bv.y);
        }
    }
    #pragma unroll
    for (int a = 0; a < 2; ++a)
        #pragma unroll
        for (int n = 0; n < 4; ++n)
            #pragma unroll
            for (int i = 0; i < 4; ++i) acc[a][n][i] = 0.0f;

    #pragma unroll 1
    for (int s = 0; s < 24; ++s) {
        CP_WAIT0();
        __syncthreads();
        if (s < 23) { stage_at(sbase + T_SLOT_OFF + ((s + 1) & 1) * BUF_BYTES, wdg, s + 1, tid); CP_COMMIT(); }
        const int rowbase = (s < 16) ? 0 : 32;
        const int k0 = (s < 16) ? s * 16 : (s - 16) * 16;
        gemm_kstep32(acc, sX, rowbase, k0, smc + T_SLOT_OFF + (s & 1) * BUF_BYTES, nb, q, c, slSel);
    }
    __syncthreads();

    #pragma unroll
    for (int nt = 0; nt < 4; ++nt) {
        const int col = nb * 32 + nt * 8 + 2 * c;
        float2 bv = *(const float2*)(bd + col);
        #pragma unroll
        for (int t = 0; t < 2; ++t) {
            const int r0 = t * 16 + q;
            *(float2*)(sX + r0 * SXS + col) =
                make_float2(sspf(acc[t][nt][0] + bv.x), sspf(acc[t][nt][1] + bv.y));
            *(float2*)(sX + (r0 + 8) * SXS + col) =
                make_float2(sspf(acc[t][nt][2] + bv.x), sspf(acc[t][nt][3] + bv.y));
        }
    }
    __syncthreads();
    {
        float4* dst = (float4*)(out + (size_t)bid * 8192);
        #pragma unroll
        for (int u = 0; u < 8; ++u) {
            int i4 = tid + u * 256;
            int row = i4 >> 6, c4 = i4 & 63;
            dst[i4] = *(const float4*)(sX + row * SXS + c4 * 4);
        }
    }
}

// ---------------------------------------------------------------------------

extern "C" void kernel_launch(void* const* d_in, const int* in_sizes, int n_in,
                              void* d_out, int out_size)
{
    const float* x        = (const float*)d_in[0];
    const float* r_ij     = (const float*)d_in[1];
    const float* f_ij     = (const float*)d_in[2];
    const float* G_i      = (const float*)d_in[3];
    const float* nmask    = (const float*)d_in[4];
    const int*   neigh    = (const int*)  d_in[5];
    const float* W_in2f   = (const float*)d_in[6];
    const float* W1       = (const float*)d_in[7];
    const float* b1       = (const float*)d_in[8];
    const float* W2       = (const float*)d_in[9];
    const float* b2       = (const float*)d_in[10];
    const float* W_f2out  = (const float*)d_in[11];
    const float* b_f2out  = (const float*)d_in[12];
    const float* W_dense  = (const float*)d_in[13];
    const float* b_dense  = (const float*)d_in[14];
    const float* W_ang    = (const float*)d_in[15];
    float* out = (float*)d_out;

    float *pXF, *pY;
    uint4 *p1s, *p2s, *pis, *pfs, *pdg;
    cudaGetSymbolAddress((void**)&pXF, g_XF);
    cudaGetSymbolAddress((void**)&pY,  g_Y);
    cudaGetSymbolAddress((void**)&p1s, g_w1s);
    cudaGetSymbolAddress((void**)&p2s, g_w2s);
    cudaGetSymbolAddress((void**)&pis, g_wis);
    cudaGetSymbolAddress((void**)&pfs, g_wfs);
    cudaGetSymbolAddress((void**)&pdg, g_wdg);

    cudaFuncSetAttribute(k1_hmma,   cudaFuncAttributeMaxDynamicSharedMemorySize, SMEM_K1_TOTAL);
    cudaFuncSetAttribute(k2_hmma,   cudaFuncAttributeMaxDynamicSharedMemorySize, SMEM_K2_TOTAL);
    cudaFuncSetAttribute(tail_hmma, cudaFuncAttributeMaxDynamicSharedMemorySize, SMEM_T_TOTAL);

    prep_all<<<320, 256>>>(W1, W2, W_in2f, W_f2out, W_dense, W_ang,
                           p1s, p2s, pis, pfs, pdg);
    k1_hmma<<<NATOMS / 32, BDIM, SMEM_K1_TOTAL>>>(x, pis, pXF);
    k2_hmma<<<NATOMS, BDIM, SMEM_K2_TOTAL>>>(
        f_ij, r_ij, nmask, neigh, p1s, p2s, b1, b2, pXF, pY);
    tail_hmma<<<NATOMS / 32, BDIM, SMEM_T_TOTAL>>>(
        pY, G_i, pfs, b_f2out, pdg, b_dense, out);
}

// round 16
// speedup vs baseline: 1.1120x; 1.1120x over previous
#include <cuda_runtime.h>
#include <cuda_bf16.h>
#include <cstdint>

// ---------------------------------------------------------------------------
// SchNet interaction block, sm_103 — v16 == v14 (best known: 491.6 us).
//   prep:  ALL weights -> pre-swizzled bf16 hi/lo chunk images (prep_all)
//   K1:    XF = x @ W_in2f                        (k1_hmma, M=32/CTA)
//   K2:    fused filter MLP + gather + aggregate  (k2_hmma, live-split A)
//   K3:    ssp((Y@Wf2o+b)@Wd + G@Wang + b)        (tail_hmma, M=32/CTA)
// GEMMs: D += Ahi*Bhi + Ahi*Blo + Alo*Bhi (bf16 splits, fp32 acc) ~1e-5 err.
// ---------------------------------------------------------------------------

#define BDIM 256
#define NATOMS 4096
#define CUTOFF 5.0f

// K2 smem layout (bytes)
#define SXS        260
#define SLOT_OFF   66560
#define BUF_BYTES  16384
#define SMEM_M_OFF 99328
#define SMEM_R_OFF 99584
#define SMEM_RED_OFF 99840
#define SMEM_K2_TOTAL 101888

// K1 smem
#define K1_SLOT_OFF 33280
#define SMEM_K1_TOTAL 66048
// tail smem
#define T_SLOT_OFF 66560
#define SMEM_T_TOTAL 99328

__device__ float g_XF[NATOMS * 256];
__device__ float g_Y [NATOMS * 256];
__device__ __align__(16) uint4 g_w1s[8 * 1024];
__device__ __align__(16) uint4 g_w2s[16 * 1024];
__device__ __align__(16) uint4 g_wis[16 * 1024];   // W_in2f
__device__ __align__(16) uint4 g_wfs[16 * 1024];   // W_f2out
__device__ __align__(16) uint4 g_wdg[24 * 1024];   // W_dense (0..15) + W_ang (16..23)

// ================= helpers =================

__device__ __forceinline__ uint32_t smem_u32(const void* p) {
    uint32_t a;
    asm("{ .reg .u64 t; cvta.to.shared.u64 t, %1; cvt.u32.u64 %0, t; }" : "=r"(a) : "l"(p));
    return a;
}
__device__ __forceinline__ float sspf(float v) {
    float e = __expf(v);
    float r = __logf(fmaf(0.5f, e, 0.5f));
    return (v > 60.0f) ? (v - 0.69314718055994531f) : r;
}
__device__ __forceinline__ uint32_t pack_bf2(float v0, float v1) {
    uint32_t r;
    asm("cvt.rn.satfinite.bf16x2.f32 %0, %1, %2;" : "=r"(r) : "f"(v1), "f"(v0));
    return r;
}
__device__ __forceinline__ float bf2_lo(uint32_t p) { return __uint_as_float(p << 16); }
__device__ __forceinline__ float bf2_hi(uint32_t p) { return __uint_as_float(p & 0xffff0000u); }

__device__ __forceinline__ void mma_bf16(float* d, uint32_t a0, uint32_t a1, uint32_t a2, uint32_t a3,
                                         uint32_t b0, uint32_t b1) {
    asm volatile("mma.sync.aligned.m16n8k16.row.col.f32.bf16.bf16.f32 "
                 "{%0,%1,%2,%3}, {%4,%5,%6,%7}, {%8,%9}, {%0,%1,%2,%3};"
                 : "+f"(d[0]), "+f"(d[1]), "+f"(d[2]), "+f"(d[3])
                 : "r"(a0), "r"(a1), "r"(a2), "r"(a3), "r"(b0), "r"(b1));
}

__device__ __forceinline__ void cp16(uint32_t dst, const void* src) {
    asm volatile("cp.async.cg.shared.global [%0], [%1], 16;" :: "r"(dst), "l"(src) : "memory");
}
#define CP_COMMIT() asm volatile("cp.async.commit_group;" ::: "memory")
#define CP_WAIT0()  asm volatile("cp.async.wait_group 0;" ::: "memory")

__device__ __forceinline__ void stage_at(uint32_t dstaddr, const uint4* ws, int s, int tid) {
    uint32_t d = dstaddr + (uint32_t)tid * 64;
    const char* g = (const char*)(ws + s * 1024) + tid * 64;
    cp16(d,      g);
    cp16(d + 16, g + 16);
    cp16(d + 32, g + 32);
    cp16(d + 48, g + 48);
}

// v7 full kstep: acc[2 mtiles][8 ntiles][4], M=64, N=256, live fp32->bf16 split
__device__ __forceinline__ void gemm_kstep(float (&acc)[2][8][4], const float* sX, int k0,
                                           const char* slot, int mt, int nb, int q, int c,
                                           int slSel) {
    uint32_t ah[2][4], al[2][4];
    #pragma unroll
    for (int t = 0; t < 2; ++t) {
        const float* bp = sX + (mt * 32 + t * 16 + q) * SXS + k0 + 2 * c;
        float2 v0 = *(const float2*)(bp);
        float2 v1 = *(const float2*)(bp + 8 * SXS);
        float2 v2 = *(const float2*)(bp + 8);
        float2 v3 = *(const float2*)(bp + 8 * SXS + 8);
        ah[t][0] = pack_bf2(v0.x, v0.y); al[t][0] = pack_bf2(v0.x - bf2_lo(ah[t][0]), v0.y - bf2_hi(ah[t][0]));
        ah[t][1] = pack_bf2(v1.x, v1.y); al[t][1] = pack_bf2(v1.x - bf2_lo(ah[t][1]), v1.y - bf2_hi(ah[t][1]));
        ah[t][2] = pack_bf2(v2.x, v2.y); al[t][2] = pack_bf2(v2.x - bf2_lo(ah[t][2]), v2.y - bf2_hi(ah[t][2]));
        ah[t][3] = pack_bf2(v3.x, v3.y); al[t][3] = pack_bf2(v3.x - bf2_lo(ah[t][3]), v3.y - bf2_hi(ah[t][3]));
    }
    #pragma unroll
    for (int nt = 0; nt < 8; ++nt) {
        const int f = nb * 64 + nt * 8 + q;
        uint4 B = *(const uint4*)(slot + f * 64 + slSel * 16);
        mma_bf16(acc[0][nt], ah[0][0], ah[0][1], ah[0][2], ah[0][3], B.x, B.y);
        mma_bf16(acc[0][nt], ah[0][0], ah[0][1], ah[0][2], ah[0][3], B.z, B.w);
        mma_bf16(acc[0][nt], al[0][0], al[0][1], al[0][2], al[0][3], B.x, B.y);
        mma_bf16(acc[1][nt], ah[1][0], ah[1][1], ah[1][2], ah[1][3], B.x, B.y);
        mma_bf16(acc[1][nt], ah[1][0], ah[1][1], ah[1][2], ah[1][3], B.z, B.w);
        mma_bf16(acc[1][nt], al[1][0], al[1][1], al[1][2], al[1][3], B.x, B.y);
    }
}

// M=32 kstep: acc[2 t][4 nt][4]; warp owns 32 N-cols (nb in 0..7)
__device__ __forceinline__ void gemm_kstep32(float (&acc)[2][4][4], const float* sX, int rowbase,
                                             int k0, const char* slot, int nb, int q, int c,
                                             int slSel) {
    uint32_t ah[2][4], al[2][4];
    #pragma unroll
    for (int t = 0; t < 2; ++t) {
        const float* bp = sX + (rowbase + t * 16 + q) * SXS + k0 + 2 * c;
        float2 v0 = *(const float2*)(bp);
        float2 v1 = *(const float2*)(bp + 8 * SXS);
        float2 v2 = *(const float2*)(bp + 8);
        float2 v3 = *(const float2*)(bp + 8 * SXS + 8);
        ah[t][0] = pack_bf2(v0.x, v0.y); al[t][0] = pack_bf2(v0.x - bf2_lo(ah[t][0]), v0.y - bf2_hi(ah[t][0]));
        ah[t][1] = pack_bf2(v1.x, v1.y); al[t][1] = pack_bf2(v1.x - bf2_lo(ah[t][1]), v1.y - bf2_hi(ah[t][1]));
        ah[t][2] = pack_bf2(v2.x, v2.y); al[t][2] = pack_bf2(v2.x - bf2_lo(ah[t][2]), v2.y - bf2_hi(ah[t][2]));
        ah[t][3] = pack_bf2(v3.x, v3.y); al[t][3] = pack_bf2(v3.x - bf2_lo(ah[t][3]), v3.y - bf2_hi(ah[t][3]));
    }
    #pragma unroll
    for (int nt = 0; nt < 4; ++nt) {
        const int f = nb * 32 + nt * 8 + q;
        uint4 B = *(const uint4*)(slot + f * 64 + slSel * 16);
        mma_bf16(acc[0][nt], ah[0][0], ah[0][1], ah[0][2], ah[0][3], B.x, B.y);
        mma_bf16(acc[0][nt], ah[0][0], ah[0][1], ah[0][2], ah[0][3], B.z, B.w);
        mma_bf16(acc[0][nt], al[0][0], al[0][1], al[0][2], al[0][3], B.x, B.y);
        mma_bf16(acc[1][nt], ah[1][0], ah[1][1], ah[1][2], ah[1][3], B.x, B.y);
        mma_bf16(acc[1][nt], ah[1][0], ah[1][1], ah[1][2], ah[1][3], B.z, B.w);
        mma_bf16(acc[1][nt], al[1][0], al[1][1], al[1][2], al[1][3], B.x, B.y);
    }
}

// ================= prep: ALL weights in one launch =================

__global__ void prep_all(const float* __restrict__ W1, const float* __restrict__ W2,
                         const float* __restrict__ Wi, const float* __restrict__ Wf,
                         const float* __restrict__ Wd, const float* __restrict__ Wa,
                         uint4* __restrict__ p1s, uint4* __restrict__ p2s,
                         uint4* __restrict__ pis, uint4* __restrict__ pfs,
                         uint4* __restrict__ pdg)
{
    int i = blockIdx.x * 256 + threadIdx.x;   // 81920 total
    const float* W; uint4* dst; int idx;
    if      (i < 8192)  { W = W1; dst = p1s;             idx = i; }
    else if (i < 24576) { W = W2; dst = p2s;             idx = i - 8192; }
    else if (i < 40960) { W = Wi; dst = pis;             idx = i - 24576; }
    else if (i < 57344) { W = Wf; dst = pfs;             idx = i - 40960; }
    else if (i < 73728) { W = Wd; dst = pdg;             idx = i - 57344; }
    else if (i < 81920) { W = Wa; dst = pdg + 16 * 1024; idx = i - 73728; }
    else return;
    const int s = idx >> 10;
    const int r = idx & 1023;
    const int f = r >> 2;
    const int slotIdx = r & 3;
    const int c = (slotIdx - (f >> 1)) & 3;
    const int k0 = s * 16 + 2 * c;
    float v0 = W[(size_t)(k0)     * 256 + f];
    float v1 = W[(size_t)(k0 + 1) * 256 + f];
    float v2 = W[(size_t)(k0 + 8) * 256 + f];
    float v3 = W[(size_t)(k0 + 9) * 256 + f];
    uint32_t h0 = pack_bf2(v0, v1);
    uint32_t h1 = pack_bf2(v2, v3);
    uint32_t l0 = pack_bf2(v0 - bf2_lo(h0), v1 - bf2_hi(h0));
    uint32_t l1 = pack_bf2(v2 - bf2_lo(h1), v3 - bf2_hi(h1));
    dst[s * 1024 + f * 4 + slotIdx] = make_uint4(h0, h1, l0, l1);
}

// ================= K2 (v7 core + cp.async F/XF) =================

__global__ __launch_bounds__(BDIM)
void k2_hmma(const float* __restrict__ f_ij, const float* __restrict__ r_ij,
             const float* __restrict__ nmask, const int* __restrict__ neigh,
             const uint4* __restrict__ w1s, const uint4* __restrict__ w2s,
             const float* __restrict__ b1, const float* __restrict__ b2,
             const float* __restrict__ XF, float* __restrict__ Y)
{
    extern __shared__ char smc[];
    float* sX   = (float*)smc;
    float* sM   = (float*)(smc + SMEM_M_OFF);
    int*   sRow = (int*)  (smc + SMEM_R_OFF);
    float* sRed = (float*)(smc + SMEM_RED_OFF);
    const uint32_t sbase = smem_u32(smc);
    const int tid = threadIdx.x, wid = tid >> 5, lane = tid & 31;
    const int q = lane >> 2, c = lane & 3;
    const int slSel = (c + (q >> 1)) & 3;
    const int mt = wid & 1, nb = wid >> 1;
    const int bid = blockIdx.x;

    // issue W1 chunk0 + F tile together (one cp.async group)
    stage_at(sbase + SLOT_OFF, w1s, 0, tid);
    {
        const char* fg = (const char*)(f_ij + (size_t)bid * 8192);
        #pragma unroll
        for (int u = 0; u < 8; ++u) {
            int unit = tid + u * 256;           // 0..2047 16B units
            int row = unit >> 5, c16 = unit & 31;
            cp16(sbase + (uint32_t)(row * 1040 + c16 * 16), fg + unit * 16);
        }
    }
    CP_COMMIT();

    if (tid < 64) {
        float r = r_ij[bid * 64 + tid];
        float m = nmask[bid * 64 + tid];
        sM[tid]   = (r <= CUTOFF) ? m : 0.0f;
        sRow[tid] = (bid >> 9) * 512 + neigh[bid * 64 + tid];
    }

    float acc[2][8][4];
    #pragma unroll
    for (int a = 0; a < 2; ++a)
        #pragma unroll
        for (int n = 0; n < 8; ++n)
            #pragma unroll
            for (int i = 0; i < 4; ++i) acc[a][n][i] = 0.0f;

    // ---- GEMM1: P = F @ W1 (8 ksteps) ----
    #pragma unroll 1
    for (int s = 0; s < 8; ++s) {
        CP_WAIT0();
        __syncthreads();
        if (s < 7) { stage_at(sbase + SLOT_OFF + ((s + 1) & 1) * BUF_BYTES, w1s, s + 1, tid); CP_COMMIT(); }
        gemm_kstep(acc, sX, s * 16, smc + SLOT_OFF + (s & 1) * BUF_BYTES, mt, nb, q, c, slSel);
    }
    __syncthreads();

    stage_at(sbase + SLOT_OFF, w2s, 0, tid);
    CP_COMMIT();

    // ---- H = ssp(P + b1) -> sX ----
    #pragma unroll
    for (int nt = 0; nt < 8; ++nt) {
        const int col = nb * 64 + nt * 8 + 2 * c;
        float2 bv = *(const float2*)(b1 + col);
        #pragma unroll
        for (int t = 0; t < 2; ++t) {
            const int r0 = mt * 32 + t * 16 + q;
            *(float2*)(sX + r0 * SXS + col) =
                make_float2(sspf(acc[t][nt][0] + bv.x), sspf(acc[t][nt][1] + bv.y));
            *(float2*)(sX + (r0 + 8) * SXS + col) =
                make_float2(sspf(acc[t][nt][2] + bv.x), sspf(acc[t][nt][3] + bv.y));
        }
    }
    #pragma unroll
    for (int a = 0; a < 2; ++a)
        #pragma unroll
        for (int n = 0; n < 8; ++n)
            #pragma unroll
            for (int i = 0; i < 4; ++i) acc[a][n][i] = 0.0f;

    // ---- GEMM2: Wf = H @ W2 (16 ksteps) ----
    #pragma unroll 1
    for (int s = 0; s < 16; ++s) {
        CP_WAIT0();
        __syncthreads();
        if (s < 15) { stage_at(sbase + SLOT_OFF + ((s + 1) & 1) * BUF_BYTES, w2s, s + 1, tid); CP_COMMIT(); }
        gemm_kstep(acc, sX, s * 16, smc + SLOT_OFF + (s & 1) * BUF_BYTES, mt, nb, q, c, slSel);
    }
    __syncthreads();

    // ---- gather XF rows via cp.async ----
    #pragma unroll
    for (int rr = 0; rr < 8; ++rr) {
        const int row = wid * 8 + rr;
        const char* src = (const char*)(XF + (size_t)sRow[row] * 256);
        cp16(sbase + (uint32_t)(row * 1040) + lane * 16,       src + lane * 16);
        cp16(sbase + (uint32_t)(row * 1040) + 512 + lane * 16, src + 512 + lane * 16);
    }
    CP_COMMIT();
    CP_WAIT0();
    __syncthreads();

    // ---- epilogue ----
    #pragma unroll
    for (int nt = 0; nt < 8; ++nt) {
        const int col = nb * 64 + nt * 8 + 2 * c;
        float2 bv = *(const float2*)(b2 + col);
        float pe = 0.0f, po = 0.0f;
        #pragma unroll
        for (int t = 0; t < 2; ++t) {
            #pragma unroll
            for (int p = 0; p < 2; ++p) {
                const int row = mt * 32 + t * 16 + q + 8 * p;
                const float m = sM[row];
                float2 x = *(const float2*)(sX + row * SXS + col);
                pe = fmaf(m * (acc[t][nt][2 * p]     + bv.x), x.x, pe);
                po = fmaf(m * (acc[t][nt][2 * p + 1] + bv.y), x.y, po);
            }
        }
        pe += __shfl_xor_sync(0xffffffffu, pe, 4);
        pe += __shfl_xor_sync(0xffffffffu, pe, 8);
        pe += __shfl_xor_sync(0xffffffffu, pe, 16);
        po += __shfl_xor_sync(0xffffffffu, po, 4);
        po += __shfl_xor_sync(0xffffffffu, po, 8);
        po += __shfl_xor_sync(0xffffffffu, po, 16);
        if (q == nt) {
            sRed[mt * 256 + col]     = pe;
            sRed[mt * 256 + col + 1] = po;
        }
    }
    __syncthreads();
    Y[(size_t)bid * 256 + tid] = sRed[tid] + sRed[256 + tid];
}

// ================= K1: XF = x @ W_in2f (HMMA, M=32/CTA) =================

__global__ __launch_bounds__(BDIM)
void k1_hmma(const float* __restrict__ x, const uint4* __restrict__ wis,
             float* __restrict__ XF)
{
    extern __shared__ char smc[];
    float* sX = (float*)smc;
    const uint32_t sbase = smem_u32(smc);
    const int tid = threadIdx.x, wid = tid >> 5, lane = tid & 31;
    const int q = lane >> 2, c = lane & 3;
    const int slSel = (c + (q >> 1)) & 3;
    const int nb = wid;
    const int bid = blockIdx.x;

    stage_at(sbase + K1_SLOT_OFF, wis, 0, tid);
    {
        const char* xg = (const char*)(x + (size_t)bid * 8192);
        #pragma unroll
        for (int u = 0; u < 8; ++u) {
            int unit = tid + u * 256;
            int row = unit >> 6, c16 = unit & 63;
            cp16(sbase + (uint32_t)(row * 1040 + c16 * 16), xg + unit * 16);
        }
    }
    CP_COMMIT();

    float acc[2][4][4];
    #pragma unroll
    for (int a = 0; a < 2; ++a)
        #pragma unroll
        for (int n = 0; n < 4; ++n)
            #pragma unroll
            for (int i = 0; i < 4; ++i) acc[a][n][i] = 0.0f;

    #pragma unroll 1
    for (int s = 0; s < 16; ++s) {
        CP_WAIT0();
        __syncthreads();
        if (s < 15) { stage_at(sbase + K1_SLOT_OFF + ((s + 1) & 1) * BUF_BYTES, wis, s + 1, tid); CP_COMMIT(); }
        gemm_kstep32(acc, sX, 0, s * 16, smc + K1_SLOT_OFF + (s & 1) * BUF_BYTES, nb, q, c, slSel);
    }
    __syncthreads();

    #pragma unroll
    for (int nt = 0; nt < 4; ++nt) {
        const int col = nb * 32 + nt * 8 + 2 * c;
        #pragma unroll
        for (int t = 0; t < 2; ++t) {
            const int r0 = t * 16 + q;
            *(float2*)(sX + r0 * SXS + col)       = make_float2(acc[t][nt][0], acc[t][nt][1]);
            *(float2*)(sX + (r0 + 8) * SXS + col) = make_float2(acc[t][nt][2], acc[t][nt][3]);
        }
    }
    __syncthreads();
    {
        float4* dst = (float4*)(XF + (size_t)bid * 8192);
        #pragma unroll
        for (int u = 0; u < 8; ++u) {
            int i4 = tid + u * 256;
            int row = i4 >> 6, c4 = i4 & 63;
            dst[i4] = *(const float4*)(sX + row * SXS + c4 * 4);
        }
    }
}

// ================= K3: tail (HMMA, M=32/CTA) =================

__global__ __launch_bounds__(BDIM)
void tail_hmma(const float* __restrict__ Yin, const float* __restrict__ Gin,
               const uint4* __restrict__ wfs, const float* __restrict__ bf,
               const uint4* __restrict__ wdg, const float* __restrict__ bd,
               float* __restrict__ out)
{
    extern __shared__ char smc[];
    float* sX = (float*)smc;
    const uint32_t sbase = smem_u32(smc);
    const int tid = threadIdx.x, wid = tid >> 5, lane = tid & 31;
    const int q = lane >> 2, c = lane & 3;
    const int slSel = (c + (q >> 1)) & 3;
    const int nb = wid;
    const int bid = blockIdx.x;

    stage_at(sbase + T_SLOT_OFF, wfs, 0, tid);
    {
        const char* yg = (const char*)(Yin + (size_t)bid * 8192);
        #pragma unroll
        for (int u = 0; u < 8; ++u) {
            int unit = tid + u * 256;
            int row = unit >> 6, c16 = unit & 63;
            cp16(sbase + (uint32_t)(row * 1040 + c16 * 16), yg + unit * 16);
        }
        const char* gg = (const char*)(Gin + (size_t)bid * 4096);
        #pragma unroll
        for (int u = 0; u < 4; ++u) {
            int unit = tid + u * 256;
            int row = unit >> 5, c16 = unit & 31;
            cp16(sbase + (uint32_t)((32 + row) * 1040 + c16 * 16), gg + unit * 16);
        }
    }
    CP_COMMIT();

    float acc[2][4][4];
    #pragma unroll
    for (int a = 0; a < 2; ++a)
        #pragma unroll
        for (int n = 0; n < 4; ++n)
            #pragma unroll
            for (int i = 0; i < 4; ++i) acc[a][n][i] = 0.0f;

    // phase A: T = Y @ W_f2out + bf
    #pragma unroll 1
    for (int s = 0; s < 16; ++s) {
        CP_WAIT0();
        __syncthreads();
        if (s < 15) { stage_at(sbase + T_SLOT_OFF + ((s + 1) & 1) * BUF_BYTES, wfs, s + 1, tid); CP_COMMIT(); }
        gemm_kstep32(acc, sX, 0, s * 16, smc + T_SLOT_OFF + (s & 1) * BUF_BYTES, nb, q, c, slSel);
    }
    __syncthreads();

    stage_at(sbase + T_SLOT_OFF, wdg, 0, tid);
    CP_COMMIT();

    #pragma unroll
    for (int nt = 0; nt < 4; ++nt) {
        const int col = nb * 32 + nt * 8 + 2 * c;
        float2 bv = *(const float2*)(bf + col);
        #pragma unroll
        for (int t = 0; t < 2; ++t) {
            const int r0 = t * 16 + q;
            *(float2*)(sX + r0 * SXS + col) =
                make_float2(acc[t][nt][0] + bv.x, acc[t][nt][1] + bv.y);
            *(float2*)(sX + (r0 + 8) * SXS + col) =
                make_float2(acc[t][nt][2] + bv.x, acc[t][nt][3] + bv.y);
        }
    }
    #pragma unroll
    for (int a = 0; a < 2; ++a)
        #pragma unroll
        for (int n = 0; n < 4; ++n)
            #pragma unroll
            for (int i = 0; i < 4; ++i) acc[a][n][i] = 0.0f;

    // phase B: U = T @ W_dense (0..15) + G @ W_ang (16..23)
    #pragma unroll 1
    for (int s = 0; s < 24; ++s) {
        CP_WAIT0();
        __syncthreads();
        if (s < 23) { stage_at(sbase + T_SLOT_OFF + ((s + 1) & 1) * BUF_BYTES, wdg, s + 1, tid); CP_COMMIT(); }
        const int rowbase = (s < 16) ? 0 : 32;
        const int k0 = (s < 16) ? s * 16 : (s - 16) * 16;
        gemm_kstep32(acc, sX, rowbase, k0, smc + T_SLOT_OFF + (s & 1) * BUF_BYTES, nb, q, c, slSel);
    }
    __syncthreads();

    #pragma unroll
    for (int nt = 0; nt < 4; ++nt) {
        const int col = nb * 32 + nt * 8 + 2 * c;
        float2 bv = *(const float2*)(bd + col);
        #pragma unroll
        for (int t = 0; t < 2; ++t) {
            const int r0 = t * 16 + q;
            *(float2*)(sX + r0 * SXS + col) =
                make_float2(sspf(acc[t][nt][0] + bv.x), sspf(acc[t][nt][1] + bv.y));
            *(float2*)(sX + (r0 + 8) * SXS + col) =
                make_float2(sspf(acc[t][nt][2] + bv.x), sspf(acc[t][nt][3] + bv.y));
        }
    }
    __syncthreads();
    {
        float4* dst = (float4*)(out + (size_t)bid * 8192);
        #pragma unroll
        for (int u = 0; u < 8; ++u) {
            int i4 = tid + u * 256;
            int row = i4 >> 6, c4 = i4 & 63;
            dst[i4] = *(const float4*)(sX + row * SXS + c4 * 4);
        }
    }
}

// ---------------------------------------------------------------------------

extern "C" void kernel_launch(void* const* d_in, const int* in_sizes, int n_in,
                              void* d_out, int out_size)
{
    const float* x        = (const float*)d_in[0];
    const float* r_ij     = (const float*)d_in[1];
    const float* f_ij     = (const float*)d_in[2];
    const float* G_i      = (const float*)d_in[3];
    const float* nmask    = (const float*)d_in[4];
    const int*   neigh    = (const int*)  d_in[5];
    const float* W_in2f   = (const float*)d_in[6];
    const float* W1       = (const float*)d_in[7];
    const float* b1       = (const float*)d_in[8];
    const float* W2       = (const float*)d_in[9];
    const float* b2       = (const float*)d_in[10];
    const float* W_f2out  = (const float*)d_in[11];
    const float* b_f2out  = (const float*)d_in[12];
    const float* W_dense  = (const float*)d_in[13];
    const float* b_dense  = (const float*)d_in[14];
    const float* W_ang    = (const float*)d_in[15];
    float* out = (float*)d_out;

    float *pXF, *pY;
    uint4 *p1s, *p2s, *pis, *pfs, *pdg;
    cudaGetSymbolAddress((void**)&pXF, g_XF);
    cudaGetSymbolAddress((void**)&pY,  g_Y);
    cudaGetSymbolAddress((void**)&p1s, g_w1s);
    cudaGetSymbolAddress((void**)&p2s, g_w2s);
    cudaGetSymbolAddress((void**)&pis, g_wis);
    cudaGetSymbolAddress((void**)&pfs, g_wfs);
    cudaGetSymbolAddress((void**)&pdg, g_wdg);

    cudaFuncSetAttribute(k1_hmma,   cudaFuncAttributeMaxDynamicSharedMemorySize, SMEM_K1_TOTAL);
    cudaFuncSetAttribute(k2_hmma,   cudaFuncAttributeMaxDynamicSharedMemorySize, SMEM_K2_TOTAL);
    cudaFuncSetAttribute(tail_hmma, cudaFuncAttributeMaxDynamicSharedMemorySize, SMEM_T_TOTAL);

    prep_all<<<320, 256>>>(W1, W2, W_in2f, W_f2out, W_dense, W_ang,
                           p1s, p2s, pis, pfs, pdg);
    k1_hmma<<<NATOMS / 32, BDIM, SMEM_K1_TOTAL>>>(x, pis, pXF);
    k2_hmma<<<NATOMS, BDIM, SMEM_K2_TOTAL>>>(
        f_ij, r_ij, nmask, neigh, p1s, p2s, b1, b2, pXF, pY);
    tail_hmma<<<NATOMS / 32, BDIM, SMEM_T_TOTAL>>>(
        pY, G_i, pfs, b_f2out, pdg, b_dense, out);
}